// round 15
// baseline (speedup 1.0000x reference)
#include <cuda_runtime.h>
#include <cuda_bf16.h>
#include <cstdint>

// Problem constants
#define DM 1024      // d_model
#define NH 16        // n_heads
#define DH 64        // d_head
#define BB 4         // batch
#define SS 2048      // seq len
#define MR (BB*SS)   // 8192 rows

// ---------------------------------------------------------------------------
// Scratch (static device globals) — bf16 hi/lo everywhere, 16B-aligned
// ---------------------------------------------------------------------------
static __device__ __align__(16) __nv_bfloat16 g_qhi[(size_t)BB * NH * SS * DH];
static __device__ __align__(16) __nv_bfloat16 g_qlo[(size_t)BB * NH * SS * DH];
static __device__ __align__(16) __nv_bfloat16 g_khi[(size_t)BB * NH * SS * DH];
static __device__ __align__(16) __nv_bfloat16 g_klo[(size_t)BB * NH * SS * DH];
static __device__ __align__(16) __nv_bfloat16 g_vhi[(size_t)BB * NH * SS * DH];
static __device__ __align__(16) __nv_bfloat16 g_vlo[(size_t)BB * NH * SS * DH];
static __device__ __align__(16) __nv_bfloat16 g_zhi[(size_t)MR * DM];
static __device__ __align__(16) __nv_bfloat16 g_zlo[(size_t)MR * DM];

static __device__ __align__(16) __nv_bfloat16 g_xhi[(size_t)MR * DM];
static __device__ __align__(16) __nv_bfloat16 g_xlo[(size_t)MR * DM];
static __device__ __align__(16) __nv_bfloat16 g_wthi[(size_t)3 * DM * DM]; // [3072][1024]
static __device__ __align__(16) __nv_bfloat16 g_wtlo[(size_t)3 * DM * DM];
static __device__ __align__(16) __nv_bfloat16 g_wohi[(size_t)DM * DM];     // [1024][1024]
static __device__ __align__(16) __nv_bfloat16 g_wolo[(size_t)DM * DM];

// ---------------------------------------------------------------------------
// Base-arch PTX helpers
// ---------------------------------------------------------------------------
__device__ __forceinline__ uint32_t smem_to_u32(const void* p) {
    uint32_t a;
    asm("{ .reg .u64 t; cvta.to.shared.u64 t, %1; cvt.u32.u64 %0, t; }"
        : "=r"(a) : "l"(p));
    return a;
}

#define CP_ASYNC16(saddr, gptr) \
    asm volatile("cp.async.cg.shared.global [%0], [%1], 16;" \
        :: "r"(saddr), "l"(gptr))
#define CP_COMMIT() asm volatile("cp.async.commit_group;" ::: "memory")
#define CP_WAIT(n)  asm volatile("cp.async.wait_group %0;" :: "n"(n) : "memory")

#define LDSM_X4(r, addr) \
    asm volatile("ldmatrix.sync.aligned.m8n8.x4.shared.b16 {%0,%1,%2,%3}, [%4];" \
        : "=r"((r)[0]), "=r"((r)[1]), "=r"((r)[2]), "=r"((r)[3]) : "r"(addr))

#define LDSM_X4_T(r, addr) \
    asm volatile("ldmatrix.sync.aligned.m8n8.x4.trans.shared.b16 {%0,%1,%2,%3}, [%4];" \
        : "=r"((r)[0]), "=r"((r)[1]), "=r"((r)[2]), "=r"((r)[3]) : "r"(addr))

#define MMA_BF16(c, a, b) \
    asm volatile("mma.sync.aligned.m16n8k16.row.col.f32.bf16.bf16.f32 " \
        "{%0,%1,%2,%3}, {%4,%5,%6,%7}, {%8,%9}, {%0,%1,%2,%3};" \
        : "+f"((c)[0]), "+f"((c)[1]), "+f"((c)[2]), "+f"((c)[3]) \
        : "r"((a)[0]), "r"((a)[1]), "r"((a)[2]), "r"((a)[3]), \
          "r"((b)[0]), "r"((b)[1]))

// ---------------------------------------------------------------------------
// fp32 -> bf16 hi/lo split helpers
// ---------------------------------------------------------------------------
__device__ __forceinline__ void splitbf(float x, __nv_bfloat16 &h, __nv_bfloat16 &l) {
    h = __float2bfloat16(x);
    l = __float2bfloat16(x - __bfloat162float(h));
}

__device__ __forceinline__ void split2u(float x, float y, uint32_t &h32, uint32_t &l32) {
    __nv_bfloat16 hx, hy, lx, ly;
    splitbf(x, hx, lx);
    splitbf(y, hy, ly);
    __nv_bfloat162 th, tl;
    th.x = hx; th.y = hy;
    tl.x = lx; tl.y = ly;
    h32 = *(uint32_t*)&th;
    l32 = *(uint32_t*)&tl;
}

// ---------------------------------------------------------------------------
// Fused prep (vectorized): split X, convert Wqkv, convert Wo.
// ---------------------------------------------------------------------------
__global__ void __launch_bounds__(256) prep_kernel(
    const float* __restrict__ src,
    const float* __restrict__ Wq, const float* __restrict__ Wk,
    const float* __restrict__ Wv, const float* __restrict__ Wo)
{
    const int bid = blockIdx.x;
    const int tid = threadIdx.x;
    if (bid < 4096) {
        size_t i = (size_t)bid * 256 + tid;
        const float4* S = (const float4*)src;
        float4 v0 = S[2 * i], v1 = S[2 * i + 1];
        uint32_t h0, l0, h1, l1, h2, l2, h3, l3;
        split2u(v0.x, v0.y, h0, l0);
        split2u(v0.z, v0.w, h1, l1);
        split2u(v1.x, v1.y, h2, l2);
        split2u(v1.z, v1.w, h3, l3);
        ((uint4*)g_xhi)[i] = make_uint4(h0, h1, h2, h3);
        ((uint4*)g_xlo)[i] = make_uint4(l0, l1, l2, l3);
    } else if (bid < 4096 + 1536) {
        int idx = (bid - 4096) * 256 + tid;
        int n  = idx % 3072;
        int kb = idx / 3072;
        int sel = n >> 10, nl = n & 1023, h = nl >> 6, d = nl & 63;
        const float* W = (sel == 0) ? Wq : (sel == 1) ? Wk : Wv;
        const float* s = W + ((size_t)h << 16) + (size_t)(kb * 8) * DH + d;
        uint32_t hh[4], ll[4];
#pragma unroll
        for (int j = 0; j < 4; j++) {
            float x0 = s[(2 * j) * DH], x1 = s[(2 * j + 1) * DH];
            split2u(x0, x1, hh[j], ll[j]);
        }
        size_t o = ((size_t)n * DM + (size_t)kb * 8) >> 3;
        ((uint4*)g_wthi)[o] = make_uint4(hh[0], hh[1], hh[2], hh[3]);
        ((uint4*)g_wtlo)[o] = make_uint4(ll[0], ll[1], ll[2], ll[3]);
    } else {
        int idx = (bid - 5632) * 256 + tid;
        int n  = idx & 1023;
        int kb = idx >> 10;
        const float* s = Wo + (size_t)(kb * 8) * DM + n;
        uint32_t hh[4], ll[4];
#pragma unroll
        for (int j = 0; j < 4; j++) {
            float x0 = s[(2 * j) * DM], x1 = s[(2 * j + 1) * DM];
            split2u(x0, x1, hh[j], ll[j]);
        }
        size_t o = ((size_t)n * DM + (size_t)kb * 8) >> 3;
        ((uint4*)g_wohi)[o] = make_uint4(hh[0], hh[1], hh[2], hh[3]);
        ((uint4*)g_wolo)[o] = make_uint4(ll[0], ll[1], ll[2], ll[3]);
    }
}

// ---------------------------------------------------------------------------
// mma.sync bf16 GEMM (3-term split). CTA 128x128, 8 warps, K-chunk 32,
// 2-stage cp.async, single __syncthreads per k-tile.  (Measured best.)
// ---------------------------------------------------------------------------
#define KC 32
#define PADE 40
#define ROWB (PADE*2)
#define TILE_B (128*ROWB)
#define STAGE_B (4*TILE_B)
#define SMEM_DYN (2*STAGE_B)

__device__ __forceinline__ void load_stage(uint32_t sb,
    const __nv_bfloat16* Ah, const __nv_bfloat16* Al,
    const __nv_bfloat16* Bh, const __nv_bfloat16* Bl,
    int m0, int n0, int k0, int tid)
{
#pragma unroll
    for (int i = 0; i < 2; i++) {
        int c   = tid + i * 256;
        int row = c >> 2;
        int ko  = (c & 3) * 8;
        uint32_t soff = (uint32_t)(row * ROWB + (c & 3) * 16);
        CP_ASYNC16(sb + 0 * TILE_B + soff, Ah + (size_t)(m0 + row) * DM + k0 + ko);
        CP_ASYNC16(sb + 1 * TILE_B + soff, Al + (size_t)(m0 + row) * DM + k0 + ko);
        CP_ASYNC16(sb + 2 * TILE_B + soff, Bh + (size_t)(n0 + row) * DM + k0 + ko);
        CP_ASYNC16(sb + 3 * TILE_B + soff, Bl + (size_t)(n0 + row) * DM + k0 + ko);
    }
}

__global__ void __launch_bounds__(256, 2) mma_gemm_kernel(
    const float* __restrict__ bias0, const float* __restrict__ bias1,
    const float* __restrict__ bias2, float* __restrict__ outp, int mode)
{
    extern __shared__ char smem[];
    const uint32_t sb0 = smem_to_u32(smem);

    const int tid  = threadIdx.x;
    const int lane = tid & 31;
    const int wid  = tid >> 5;
    const int wm   = wid & 3;
    const int wn   = wid >> 2;
    const int m0   = blockIdx.y * 128;
    const int n0   = blockIdx.x * 128;

    const __nv_bfloat16* Ahi = (mode == 0) ? g_xhi  : g_zhi;
    const __nv_bfloat16* Alo = (mode == 0) ? g_xlo  : g_zlo;
    const __nv_bfloat16* Bhi = (mode == 0) ? g_wthi : g_wohi;
    const __nv_bfloat16* Blo = (mode == 0) ? g_wtlo : g_wolo;

    float c[2][8][4];
#pragma unroll
    for (int i = 0; i < 2; i++)
#pragma unroll
        for (int j = 0; j < 8; j++)
#pragma unroll
            for (int q = 0; q < 4; q++) c[i][j][q] = 0.f;

    const uint32_t a_row = (uint32_t)(wm * 32 + ((lane >> 3) & 1) * 8 + (lane & 7));
    const uint32_t a_kof = (uint32_t)((lane >> 4) * 8);
    const uint32_t b_row = (uint32_t)(wn * 64 + (lane >> 4) * 8 + (lane & 7));
    const uint32_t b_kof = (uint32_t)(((lane >> 3) & 1) * 8);

    load_stage(sb0, Ahi, Alo, Bhi, Blo, m0, n0, 0, tid);
    CP_COMMIT();

#pragma unroll 1
    for (int t = 0; t < DM / KC; t++) {
        CP_WAIT(0);
        __syncthreads();
        if (t + 1 < DM / KC) {
            load_stage(sb0 + ((t + 1) & 1) * STAGE_B, Ahi, Alo, Bhi, Blo,
                       m0, n0, (t + 1) * KC, tid);
            CP_COMMIT();
        }

        const uint32_t st = sb0 + (t & 1) * STAGE_B;
#pragma unroll
        for (int ks = 0; ks < 2; ks++) {
            const uint32_t k0 = (uint32_t)(ks * 16);
            uint32_t ah[8], al[8];
#pragma unroll
            for (int mf = 0; mf < 2; mf++) {
                uint32_t ad = st + (a_row + mf * 16) * ROWB + (k0 + a_kof) * 2;
                LDSM_X4(&ah[4 * mf], ad);
                LDSM_X4(&al[4 * mf], ad + TILE_B);
            }
#pragma unroll
            for (int nq = 0; nq < 4; nq++) {
                uint32_t bh4[4], bl4[4];
                uint32_t bd = st + 2 * TILE_B + (b_row + nq * 16) * ROWB
                            + (k0 + b_kof) * 2;
                LDSM_X4(bh4, bd);
                LDSM_X4(bl4, bd + TILE_B);
#pragma unroll
                for (int mf = 0; mf < 2; mf++) {
                    MMA_BF16(c[mf][2 * nq],     &ah[4 * mf], &bh4[0]);
                    MMA_BF16(c[mf][2 * nq + 1], &ah[4 * mf], &bh4[2]);
                    MMA_BF16(c[mf][2 * nq],     &ah[4 * mf], &bl4[0]);
                    MMA_BF16(c[mf][2 * nq + 1], &ah[4 * mf], &bl4[2]);
                    MMA_BF16(c[mf][2 * nq],     &al[4 * mf], &bh4[0]);
                    MMA_BF16(c[mf][2 * nq + 1], &al[4 * mf], &bh4[2]);
                }
            }
        }
    }

    const int rb0 = m0 + wm * 32 + (lane >> 2);
    const int cb  = 2 * (lane & 3);

    if (mode == 0) {
        const int sel = n0 >> 10;
        const int nl  = (n0 & 1023) + wn * 64;
        const int h   = nl >> 6;
        __nv_bfloat16* dsth = (sel == 0) ? g_qhi : (sel == 1) ? g_khi : g_vhi;
        __nv_bfloat16* dstl = (sel == 0) ? g_qlo : (sel == 1) ? g_klo : g_vlo;
        const float* bias = ((sel == 0) ? bias0 : (sel == 1) ? bias1 : bias2)
                          + h * DH;
        const int b  = rb0 >> 11;
        const int s0 = rb0 & (SS - 1);
        size_t base = ((size_t)(b * NH + h) * SS) * DH;
#pragma unroll
        for (int mf = 0; mf < 2; mf++) {
#pragma unroll
            for (int nf = 0; nf < 8; nf++) {
                int d = nf * 8 + cb;
                float bx = bias[d], by = bias[d + 1];
                uint32_t h0, l0, h1, l1;
                split2u(c[mf][nf][0] + bx, c[mf][nf][1] + by, h0, l0);
                split2u(c[mf][nf][2] + bx, c[mf][nf][3] + by, h1, l1);
                size_t i0 = base + (size_t)(s0 + mf * 16) * DH + d;
                size_t i1 = base + (size_t)(s0 + mf * 16 + 8) * DH + d;
                *(uint32_t*)(dsth + i0) = h0;
                *(uint32_t*)(dstl + i0) = l0;
                *(uint32_t*)(dsth + i1) = h1;
                *(uint32_t*)(dstl + i1) = l1;
            }
        }
    } else {
        const int nb = n0 + wn * 64;
        const float* bias = bias0 + nb;
        float* op = outp + (size_t)rb0 * DM + nb;
#pragma unroll
        for (int mf = 0; mf < 2; mf++) {
#pragma unroll
            for (int nf = 0; nf < 8; nf++) {
                int d = nf * 8 + cb;
                float bx = bias[d], by = bias[d + 1];
                float2 v0 = make_float2(c[mf][nf][0] + bx, c[mf][nf][1] + by);
                float2 v1 = make_float2(c[mf][nf][2] + bx, c[mf][nf][3] + by);
                *(float2*)(op + (size_t)(mf * 16) * DM + d)     = v0;
                *(float2*)(op + (size_t)(mf * 16 + 8) * DM + d) = v1;
            }
        }
    }
}

// ---------------------------------------------------------------------------
// Causal flash attention (mma.sync bf16, 3-term split).
// Two warp-uniform tile paths:
//  - FULL (kv0+63 <= wr0): exact R13 hot loops, zero inner branches, no mask.
//  - PARTIAL (diagonal): ngmax-bounded groups + mask (bit-identical results).
// No __syncthreads inside the guarded body, so per-warp divergence is safe.
// ---------------------------------------------------------------------------
#define ADHP 72
#define AROWB (ADHP*2)
#define ATILE (64*AROWB)
#define AOFF_KHI 0
#define AOFF_KLO (ATILE)
#define AOFF_VHI (2*ATILE)
#define AOFF_VLO (3*ATILE)
#define ASTAGE (4*ATILE)               // 36864
#define ASMEM (2*ASTAGE)               // 73728

__device__ __forceinline__ void attn_load(uint32_t sbase,
    const __nv_bfloat16* Kh, const __nv_bfloat16* Kl,
    const __nv_bfloat16* Vh, const __nv_bfloat16* Vl,
    int j0, int tid)
{
#pragma unroll
    for (int i = 0; i < 2; i++) {
        int c   = tid + i * 256;
        int row = c >> 3;
        int co  = (c & 7) * 8;
        uint32_t soff = (uint32_t)(row * AROWB + co * 2);
        size_t goff = (size_t)(j0 + row) * DH + co;
        CP_ASYNC16(sbase + AOFF_KHI + soff, Kh + goff);
        CP_ASYNC16(sbase + AOFF_KLO + soff, Kl + goff);
        CP_ASYNC16(sbase + AOFF_VHI + soff, Vh + goff);
        CP_ASYNC16(sbase + AOFF_VLO + soff, Vl + goff);
    }
}

__global__ void __launch_bounds__(256, 1) attn_mma_kernel()
{
    extern __shared__ char smem[];
    const uint32_t sb0 = smem_to_u32(smem);

    const int tid  = threadIdx.x;
    const int lane = tid & 31;
    const int wq   = tid >> 5;
    const int bh   = blockIdx.y;
    const int qb   = (int)gridDim.x - 1 - (int)blockIdx.x;
    const int q0   = qb * 128;
    const int wr0  = q0 + wq * 16;

    const size_t hb = (size_t)bh * SS * DH;
    const __nv_bfloat16* Kh = g_khi + hb;
    const __nv_bfloat16* Kl = g_klo + hb;
    const __nv_bfloat16* Vh = g_vhi + hb;
    const __nv_bfloat16* Vl = g_vlo + hb;

    const int r0g = wr0 + (lane >> 2);
    const int r1g = r0g + 8;
    uint32_t qh[16], ql[16];
    {
        const __nv_bfloat16* Qh = g_qhi + hb;
        const __nv_bfloat16* Ql = g_qlo + hb;
        const int kb = 2 * (lane & 3);
#pragma unroll
        for (int t = 0; t < 4; t++) {
            int k0 = 16 * t + kb;
            qh[4*t+0] = *(const uint32_t*)(Qh + (size_t)r0g * DH + k0);
            qh[4*t+1] = *(const uint32_t*)(Qh + (size_t)r1g * DH + k0);
            qh[4*t+2] = *(const uint32_t*)(Qh + (size_t)r0g * DH + k0 + 8);
            qh[4*t+3] = *(const uint32_t*)(Qh + (size_t)r1g * DH + k0 + 8);
            ql[4*t+0] = *(const uint32_t*)(Ql + (size_t)r0g * DH + k0);
            ql[4*t+1] = *(const uint32_t*)(Ql + (size_t)r1g * DH + k0);
            ql[4*t+2] = *(const uint32_t*)(Ql + (size_t)r0g * DH + k0 + 8);
            ql[4*t+3] = *(const uint32_t*)(Ql + (size_t)r1g * DH + k0 + 8);
        }
    }

    float o[8][4];
#pragma unroll
    for (int i = 0; i < 8; i++)
#pragma unroll
        for (int j = 0; j < 4; j++) o[i][j] = 0.f;
    float m0 = -1e30f, m1 = -1e30f, l0 = 0.f, l1 = 0.f;

    const int kgrp = lane >> 3, kln = lane & 7;
    const uint32_t krow = (uint32_t)((kgrp >> 1) * 8 + kln);
    const uint32_t kcol = (uint32_t)((kgrp & 1) * 8);
    const uint32_t vrow = (uint32_t)((kgrp & 1) * 8 + kln);
    const uint32_t vcol = (uint32_t)((kgrp >> 1) * 8);

    const int ntk = 2 * qb + 2;
    attn_load(sb0, Kh, Kl, Vh, Vl, 0, tid);
    CP_COMMIT();

#pragma unroll 1
    for (int t = 0; t < ntk; t++) {
        CP_WAIT(0);
        __syncthreads();
        if (t + 1 < ntk) {
            attn_load(sb0 + ((t + 1) & 1) * ASTAGE, Kh, Kl, Vh, Vl,
                      (t + 1) * 64, tid);
            CP_COMMIT();
        }

        const int kv0 = t * 64;
        if (kv0 <= wr0 + 15) {
            const uint32_t st = sb0 + (t & 1) * ASTAGE;
            const bool full = (kv0 + 63 <= wr0);
            int ngmax = 4;

            float s[8][4];
#pragma unroll
            for (int i = 0; i < 8; i++)
#pragma unroll
                for (int j = 0; j < 4; j++) s[i][j] = 0.f;

            if (full) {
                // ---- HOT PATH: exact R13 loops, no inner branches ----
#pragma unroll
                for (int dk = 0; dk < 4; dk++) {
#pragma unroll
                    for (int ng = 0; ng < 4; ng++) {
                        uint32_t kh4[4], kl4[4];
                        uint32_t ka = st + AOFF_KHI
                                    + (uint32_t)(ng * 16 + krow) * AROWB
                                    + (uint32_t)(dk * 16 + kcol) * 2;
                        LDSM_X4(kh4, ka);
                        LDSM_X4(kl4, ka + (AOFF_KLO - AOFF_KHI));
                        MMA_BF16(s[2*ng],   &qh[4*dk], &kh4[0]);
                        MMA_BF16(s[2*ng],   &ql[4*dk], &kh4[0]);
                        MMA_BF16(s[2*ng],   &qh[4*dk], &kl4[0]);
                        MMA_BF16(s[2*ng+1], &qh[4*dk], &kh4[2]);
                        MMA_BF16(s[2*ng+1], &ql[4*dk], &kh4[2]);
                        MMA_BF16(s[2*ng+1], &qh[4*dk], &kl4[2]);
                    }
                }
#pragma unroll
                for (int nt = 0; nt < 8; nt++)
#pragma unroll
                    for (int e = 0; e < 4; e++) s[nt][e] *= 0.125f;
            } else {
                // ---- DIAGONAL TILE: ngmax-bounded groups + mask ----
                ngmax = ((wr0 + 15 - kv0) >> 4) + 1;       // 1..4
#pragma unroll 1
                for (int ng = 0; ng < 4; ng++) {
                    if (ng >= ngmax) break;
#pragma unroll
                    for (int dk = 0; dk < 4; dk++) {
                        uint32_t kh4[4], kl4[4];
                        uint32_t ka = st + AOFF_KHI
                                    + (uint32_t)(ng * 16 + krow) * AROWB
                                    + (uint32_t)(dk * 16 + kcol) * 2;
                        LDSM_X4(kh4, ka);
                        LDSM_X4(kl4, ka + (AOFF_KLO - AOFF_KHI));
                        MMA_BF16(s[2*ng],   &qh[4*dk], &kh4[0]);
                        MMA_BF16(s[2*ng],   &ql[4*dk], &kh4[0]);
                        MMA_BF16(s[2*ng],   &qh[4*dk], &kl4[0]);
                        MMA_BF16(s[2*ng+1], &qh[4*dk], &kh4[2]);
                        MMA_BF16(s[2*ng+1], &ql[4*dk], &kh4[2]);
                        MMA_BF16(s[2*ng+1], &qh[4*dk], &kl4[2]);
                    }
                }
                const int colb = kv0 + 2 * (lane & 3);
#pragma unroll
                for (int nt = 0; nt < 8; nt++) {
                    int c0 = colb + 8 * nt;
#pragma unroll
                    for (int e = 0; e < 4; e++) {
                        float v = s[nt][e] * 0.125f;
                        int col = c0 + (e & 1);
                        int row = (e < 2) ? r0g : r1g;
                        if (col > row) v = -1e30f;
                        s[nt][e] = v;
                    }
                }
            }

            // ---- online softmax (common) ----
            float t0 = -1e30f, t1 = -1e30f;
#pragma unroll
            for (int nt = 0; nt < 8; nt++) {
                t0 = fmaxf(t0, fmaxf(s[nt][0], s[nt][1]));
                t1 = fmaxf(t1, fmaxf(s[nt][2], s[nt][3]));
            }
            t0 = fmaxf(t0, __shfl_xor_sync(0xffffffff, t0, 1));
            t0 = fmaxf(t0, __shfl_xor_sync(0xffffffff, t0, 2));
            t1 = fmaxf(t1, __shfl_xor_sync(0xffffffff, t1, 1));
            t1 = fmaxf(t1, __shfl_xor_sync(0xffffffff, t1, 2));

            float mn0 = fmaxf(m0, t0), mn1 = fmaxf(m1, t1);
            float cr0 = __expf(m0 - mn0), cr1 = __expf(m1 - mn1);
            m0 = mn0; m1 = mn1;

            float ts0 = 0.f, ts1 = 0.f;
#pragma unroll
            for (int nt = 0; nt < 8; nt++) {
                s[nt][0] = __expf(s[nt][0] - m0);
                s[nt][1] = __expf(s[nt][1] - m0);
                s[nt][2] = __expf(s[nt][2] - m1);
                s[nt][3] = __expf(s[nt][3] - m1);
                ts0 += s[nt][0] + s[nt][1];
                ts1 += s[nt][2] + s[nt][3];
            }
            ts0 += __shfl_xor_sync(0xffffffff, ts0, 1);
            ts0 += __shfl_xor_sync(0xffffffff, ts0, 2);
            ts1 += __shfl_xor_sync(0xffffffff, ts1, 1);
            ts1 += __shfl_xor_sync(0xffffffff, ts1, 2);
            l0 = l0 * cr0 + ts0;
            l1 = l1 * cr1 + ts1;

#pragma unroll
            for (int nt = 0; nt < 8; nt++) {
                o[nt][0] *= cr0; o[nt][1] *= cr0;
                o[nt][2] *= cr1; o[nt][3] *= cr1;
            }

            // ---- O += P V ----
            if (full) {
                // HOT PATH: exact R13 loops
#pragma unroll
                for (int tp = 0; tp < 4; tp++) {
                    uint32_t ph[4], pl[4];
                    split2u(s[2*tp][0],   s[2*tp][1],   ph[0], pl[0]);
                    split2u(s[2*tp][2],   s[2*tp][3],   ph[1], pl[1]);
                    split2u(s[2*tp+1][0], s[2*tp+1][1], ph[2], pl[2]);
                    split2u(s[2*tp+1][2], s[2*tp+1][3], ph[3], pl[3]);
#pragma unroll
                    for (int dn2 = 0; dn2 < 4; dn2++) {
                        uint32_t vh4[4], vl4[4];
                        uint32_t va = st + AOFF_VHI
                                    + (uint32_t)(tp * 16 + vrow) * AROWB
                                    + (uint32_t)(dn2 * 16 + vcol) * 2;
                        LDSM_X4_T(vh4, va);
                        LDSM_X4_T(vl4, va + (AOFF_VLO - AOFF_VHI));
                        MMA_BF16(o[2*dn2],   ph, &vh4[0]);
                        MMA_BF16(o[2*dn2],   pl, &vh4[0]);
                        MMA_BF16(o[2*dn2],   ph, &vl4[0]);
                        MMA_BF16(o[2*dn2+1], ph, &vh4[2]);
                        MMA_BF16(o[2*dn2+1], pl, &vh4[2]);
                        MMA_BF16(o[2*dn2+1], ph, &vl4[2]);
                    }
                }
            } else {
                // DIAGONAL TILE: skip tp groups whose p are all exactly 0
#pragma unroll 1
                for (int tp = 0; tp < 4; tp++) {
                    if (tp >= ngmax) break;
                    uint32_t ph[4], pl[4];
                    split2u(s[2*tp][0],   s[2*tp][1],   ph[0], pl[0]);
                    split2u(s[2*tp][2],   s[2*tp][3],   ph[1], pl[1]);
                    split2u(s[2*tp+1][0], s[2*tp+1][1], ph[2], pl[2]);
                    split2u(s[2*tp+1][2], s[2*tp+1][3], ph[3], pl[3]);
#pragma unroll
                    for (int dn2 = 0; dn2 < 4; dn2++) {
                        uint32_t vh4[4], vl4[4];
                        uint32_t va = st + AOFF_VHI
                                    + (uint32_t)(tp * 16 + vrow) * AROWB
                                    + (uint32_t)(dn2 * 16 + vcol) * 2;
                        LDSM_X4_T(vh4, va);
                        LDSM_X4_T(vl4, va + (AOFF_VLO - AOFF_VHI));
                        MMA_BF16(o[2*dn2],   ph, &vh4[0]);
                        MMA_BF16(o[2*dn2],   pl, &vh4[0]);
                        MMA_BF16(o[2*dn2],   ph, &vl4[0]);
                        MMA_BF16(o[2*dn2+1], ph, &vh4[2]);
                        MMA_BF16(o[2*dn2+1], pl, &vh4[2]);
                        MMA_BF16(o[2*dn2+1], ph, &vl4[2]);
                    }
                }
            }
        }
    }

    const float i0 = 1.f / l0, i1 = 1.f / l1;
    const int b = bh >> 4, h = bh & 15;
    const int cb = 2 * (lane & 3);
#pragma unroll
    for (int nt = 0; nt < 8; nt++) {
        int d = 8 * nt + cb;
        size_t z0 = ((size_t)(b * SS + r0g) * NH + h) * DH + d;
        size_t z1 = ((size_t)(b * SS + r1g) * NH + h) * DH + d;
        uint32_t h32, l32;
        split2u(o[nt][0] * i0, o[nt][1] * i0, h32, l32);
        *(uint32_t*)(g_zhi + z0) = h32;
        *(uint32_t*)(g_zlo + z0) = l32;
        split2u(o[nt][2] * i1, o[nt][3] * i1, h32, l32);
        *(uint32_t*)(g_zhi + z1) = h32;
        *(uint32_t*)(g_zlo + z1) = l32;
    }
}

// ---------------------------------------------------------------------------
// Launch sequence
// ---------------------------------------------------------------------------
extern "C" void kernel_launch(void* const* d_in, const int* in_sizes, int n_in,
                              void* d_out, int out_size)
{
    (void)in_sizes; (void)n_in; (void)out_size;
    const float* resid = (const float*)d_in[0];
    const float* Wq    = (const float*)d_in[1];
    const float* Wk    = (const float*)d_in[2];
    const float* Wv    = (const float*)d_in[3];
    const float* Wo    = (const float*)d_in[4];
    const float* bq    = (const float*)d_in[5];
    const float* bk    = (const float*)d_in[6];
    const float* bv    = (const float*)d_in[7];
    const float* bo    = (const float*)d_in[8];
    float* out = (float*)d_out;

    cudaFuncSetAttribute(mma_gemm_kernel,
                         cudaFuncAttributeMaxDynamicSharedMemorySize, SMEM_DYN);
    cudaFuncSetAttribute(attn_mma_kernel,
                         cudaFuncAttributeMaxDynamicSharedMemorySize, ASMEM);

    prep_kernel<<<6144, 256>>>(resid, Wq, Wk, Wv, Wo);

    mma_gemm_kernel<<<dim3(24, 64), 256, SMEM_DYN>>>(bq, bk, bv, nullptr, 0);
    attn_mma_kernel<<<dim3(16, 64), 256, ASMEM>>>();
    mma_gemm_kernel<<<dim3(8, 64), 256, SMEM_DYN>>>(bo, bo, bo, out, 1);
}

// round 16
// speedup vs baseline: 1.1572x; 1.1572x over previous
#include <cuda_runtime.h>
#include <cuda_bf16.h>
#include <cstdint>

// Problem constants
#define DM 1024      // d_model
#define NH 16        // n_heads
#define DH 64        // d_head
#define BB 4         // batch
#define SS 2048      // seq len
#define MR (BB*SS)   // 8192 rows

// ---------------------------------------------------------------------------
// Scratch (static device globals) — bf16 hi/lo everywhere, 16B-aligned
// ---------------------------------------------------------------------------
static __device__ __align__(16) __nv_bfloat16 g_qhi[(size_t)BB * NH * SS * DH];
static __device__ __align__(16) __nv_bfloat16 g_qlo[(size_t)BB * NH * SS * DH];
static __device__ __align__(16) __nv_bfloat16 g_khi[(size_t)BB * NH * SS * DH];
static __device__ __align__(16) __nv_bfloat16 g_klo[(size_t)BB * NH * SS * DH];
static __device__ __align__(16) __nv_bfloat16 g_vhi[(size_t)BB * NH * SS * DH];
static __device__ __align__(16) __nv_bfloat16 g_vlo[(size_t)BB * NH * SS * DH];
static __device__ __align__(16) __nv_bfloat16 g_zhi[(size_t)MR * DM];
static __device__ __align__(16) __nv_bfloat16 g_zlo[(size_t)MR * DM];

static __device__ __align__(16) __nv_bfloat16 g_xhi[(size_t)MR * DM];
static __device__ __align__(16) __nv_bfloat16 g_xlo[(size_t)MR * DM];
static __device__ __align__(16) __nv_bfloat16 g_wthi[(size_t)3 * DM * DM]; // [3072][1024]
static __device__ __align__(16) __nv_bfloat16 g_wtlo[(size_t)3 * DM * DM];
static __device__ __align__(16) __nv_bfloat16 g_wohi[(size_t)DM * DM];     // [1024][1024]
static __device__ __align__(16) __nv_bfloat16 g_wolo[(size_t)DM * DM];

// ---------------------------------------------------------------------------
// Base-arch PTX helpers
// ---------------------------------------------------------------------------
__device__ __forceinline__ uint32_t smem_to_u32(const void* p) {
    uint32_t a;
    asm("{ .reg .u64 t; cvta.to.shared.u64 t, %1; cvt.u32.u64 %0, t; }"
        : "=r"(a) : "l"(p));
    return a;
}

#define CP_ASYNC16(saddr, gptr) \
    asm volatile("cp.async.cg.shared.global [%0], [%1], 16;" \
        :: "r"(saddr), "l"(gptr))
#define CP_COMMIT() asm volatile("cp.async.commit_group;" ::: "memory")
#define CP_WAIT(n)  asm volatile("cp.async.wait_group %0;" :: "n"(n) : "memory")

#define LDSM_X4(r, addr) \
    asm volatile("ldmatrix.sync.aligned.m8n8.x4.shared.b16 {%0,%1,%2,%3}, [%4];" \
        : "=r"((r)[0]), "=r"((r)[1]), "=r"((r)[2]), "=r"((r)[3]) : "r"(addr))

#define LDSM_X4_T(r, addr) \
    asm volatile("ldmatrix.sync.aligned.m8n8.x4.trans.shared.b16 {%0,%1,%2,%3}, [%4];" \
        : "=r"((r)[0]), "=r"((r)[1]), "=r"((r)[2]), "=r"((r)[3]) : "r"(addr))

#define MMA_BF16(c, a, b) \
    asm volatile("mma.sync.aligned.m16n8k16.row.col.f32.bf16.bf16.f32 " \
        "{%0,%1,%2,%3}, {%4,%5,%6,%7}, {%8,%9}, {%0,%1,%2,%3};" \
        : "+f"((c)[0]), "+f"((c)[1]), "+f"((c)[2]), "+f"((c)[3]) \
        : "r"((a)[0]), "r"((a)[1]), "r"((a)[2]), "r"((a)[3]), \
          "r"((b)[0]), "r"((b)[1]))

// ---------------------------------------------------------------------------
// fp32 -> bf16 hi/lo split helpers
// ---------------------------------------------------------------------------
__device__ __forceinline__ void splitbf(float x, __nv_bfloat16 &h, __nv_bfloat16 &l) {
    h = __float2bfloat16(x);
    l = __float2bfloat16(x - __bfloat162float(h));
}

__device__ __forceinline__ void split2u(float x, float y, uint32_t &h32, uint32_t &l32) {
    __nv_bfloat16 hx, hy, lx, ly;
    splitbf(x, hx, lx);
    splitbf(y, hy, ly);
    __nv_bfloat162 th, tl;
    th.x = hx; th.y = hy;
    tl.x = lx; tl.y = ly;
    h32 = *(uint32_t*)&th;
    l32 = *(uint32_t*)&tl;
}

// ---------------------------------------------------------------------------
// Fused prep (vectorized): split X, convert Wqkv, convert Wo.
// blocks [0,4096): split_x ; [4096,5632): conv_wqkv ; [5632,6144): conv_wo
// ---------------------------------------------------------------------------
__global__ void __launch_bounds__(256) prep_kernel(
    const float* __restrict__ src,
    const float* __restrict__ Wq, const float* __restrict__ Wk,
    const float* __restrict__ Wv, const float* __restrict__ Wo)
{
    const int bid = blockIdx.x;
    const int tid = threadIdx.x;
    if (bid < 4096) {
        size_t i = (size_t)bid * 256 + tid;
        const float4* S = (const float4*)src;
        float4 v0 = S[2 * i], v1 = S[2 * i + 1];
        uint32_t h0, l0, h1, l1, h2, l2, h3, l3;
        split2u(v0.x, v0.y, h0, l0);
        split2u(v0.z, v0.w, h1, l1);
        split2u(v1.x, v1.y, h2, l2);
        split2u(v1.z, v1.w, h3, l3);
        ((uint4*)g_xhi)[i] = make_uint4(h0, h1, h2, h3);
        ((uint4*)g_xlo)[i] = make_uint4(l0, l1, l2, l3);
    } else if (bid < 4096 + 1536) {
        int idx = (bid - 4096) * 256 + tid;
        int n  = idx % 3072;
        int kb = idx / 3072;
        int sel = n >> 10, nl = n & 1023, h = nl >> 6, d = nl & 63;
        const float* W = (sel == 0) ? Wq : (sel == 1) ? Wk : Wv;
        const float* s = W + ((size_t)h << 16) + (size_t)(kb * 8) * DH + d;
        uint32_t hh[4], ll[4];
#pragma unroll
        for (int j = 0; j < 4; j++) {
            float x0 = s[(2 * j) * DH], x1 = s[(2 * j + 1) * DH];
            split2u(x0, x1, hh[j], ll[j]);
        }
        size_t o = ((size_t)n * DM + (size_t)kb * 8) >> 3;
        ((uint4*)g_wthi)[o] = make_uint4(hh[0], hh[1], hh[2], hh[3]);
        ((uint4*)g_wtlo)[o] = make_uint4(ll[0], ll[1], ll[2], ll[3]);
    } else {
        int idx = (bid - 5632) * 256 + tid;
        int n  = idx & 1023;
        int kb = idx >> 10;
        const float* s = Wo + (size_t)(kb * 8) * DM + n;
        uint32_t hh[4], ll[4];
#pragma unroll
        for (int j = 0; j < 4; j++) {
            float x0 = s[(2 * j) * DM], x1 = s[(2 * j + 1) * DM];
            split2u(x0, x1, hh[j], ll[j]);
        }
        size_t o = ((size_t)n * DM + (size_t)kb * 8) >> 3;
        ((uint4*)g_wohi)[o] = make_uint4(hh[0], hh[1], hh[2], hh[3]);
        ((uint4*)g_wolo)[o] = make_uint4(ll[0], ll[1], ll[2], ll[3]);
    }
}

// ---------------------------------------------------------------------------
// mma.sync bf16 GEMM (3-term split). CTA 128x128, 8 warps, K-chunk 32,
// 2-stage cp.async, single __syncthreads per k-tile.  (Measured best.)
// mode 0: A=X, B=Wqkv^T -> g_{q,k,v}{hi,lo} + bias
// mode 1: A=Z, B=Wo^T   -> fp32 out + bO (bias0)
// ---------------------------------------------------------------------------
#define KC 32
#define PADE 40
#define ROWB (PADE*2)
#define TILE_B (128*ROWB)
#define STAGE_B (4*TILE_B)
#define SMEM_DYN (2*STAGE_B)

__device__ __forceinline__ void load_stage(uint32_t sb,
    const __nv_bfloat16* Ah, const __nv_bfloat16* Al,
    const __nv_bfloat16* Bh, const __nv_bfloat16* Bl,
    int m0, int n0, int k0, int tid)
{
#pragma unroll
    for (int i = 0; i < 2; i++) {
        int c   = tid + i * 256;
        int row = c >> 2;
        int ko  = (c & 3) * 8;
        uint32_t soff = (uint32_t)(row * ROWB + (c & 3) * 16);
        CP_ASYNC16(sb + 0 * TILE_B + soff, Ah + (size_t)(m0 + row) * DM + k0 + ko);
        CP_ASYNC16(sb + 1 * TILE_B + soff, Al + (size_t)(m0 + row) * DM + k0 + ko);
        CP_ASYNC16(sb + 2 * TILE_B + soff, Bh + (size_t)(n0 + row) * DM + k0 + ko);
        CP_ASYNC16(sb + 3 * TILE_B + soff, Bl + (size_t)(n0 + row) * DM + k0 + ko);
    }
}

__global__ void __launch_bounds__(256, 2) mma_gemm_kernel(
    const float* __restrict__ bias0, const float* __restrict__ bias1,
    const float* __restrict__ bias2, float* __restrict__ outp, int mode)
{
    extern __shared__ char smem[];
    const uint32_t sb0 = smem_to_u32(smem);

    const int tid  = threadIdx.x;
    const int lane = tid & 31;
    const int wid  = tid >> 5;
    const int wm   = wid & 3;
    const int wn   = wid >> 2;
    const int m0   = blockIdx.y * 128;
    const int n0   = blockIdx.x * 128;

    const __nv_bfloat16* Ahi = (mode == 0) ? g_xhi  : g_zhi;
    const __nv_bfloat16* Alo = (mode == 0) ? g_xlo  : g_zlo;
    const __nv_bfloat16* Bhi = (mode == 0) ? g_wthi : g_wohi;
    const __nv_bfloat16* Blo = (mode == 0) ? g_wtlo : g_wolo;

    float c[2][8][4];
#pragma unroll
    for (int i = 0; i < 2; i++)
#pragma unroll
        for (int j = 0; j < 8; j++)
#pragma unroll
            for (int q = 0; q < 4; q++) c[i][j][q] = 0.f;

    const uint32_t a_row = (uint32_t)(wm * 32 + ((lane >> 3) & 1) * 8 + (lane & 7));
    const uint32_t a_kof = (uint32_t)((lane >> 4) * 8);
    const uint32_t b_row = (uint32_t)(wn * 64 + (lane >> 4) * 8 + (lane & 7));
    const uint32_t b_kof = (uint32_t)(((lane >> 3) & 1) * 8);

    load_stage(sb0, Ahi, Alo, Bhi, Blo, m0, n0, 0, tid);
    CP_COMMIT();

#pragma unroll 1
    for (int t = 0; t < DM / KC; t++) {
        CP_WAIT(0);
        __syncthreads();
        if (t + 1 < DM / KC) {
            load_stage(sb0 + ((t + 1) & 1) * STAGE_B, Ahi, Alo, Bhi, Blo,
                       m0, n0, (t + 1) * KC, tid);
            CP_COMMIT();
        }

        const uint32_t st = sb0 + (t & 1) * STAGE_B;
#pragma unroll
        for (int ks = 0; ks < 2; ks++) {
            const uint32_t k0 = (uint32_t)(ks * 16);
            uint32_t ah[8], al[8];
#pragma unroll
            for (int mf = 0; mf < 2; mf++) {
                uint32_t ad = st + (a_row + mf * 16) * ROWB + (k0 + a_kof) * 2;
                LDSM_X4(&ah[4 * mf], ad);
                LDSM_X4(&al[4 * mf], ad + TILE_B);
            }
#pragma unroll
            for (int nq = 0; nq < 4; nq++) {
                uint32_t bh4[4], bl4[4];
                uint32_t bd = st + 2 * TILE_B + (b_row + nq * 16) * ROWB
                            + (k0 + b_kof) * 2;
                LDSM_X4(bh4, bd);
                LDSM_X4(bl4, bd + TILE_B);
#pragma unroll
                for (int mf = 0; mf < 2; mf++) {
                    MMA_BF16(c[mf][2 * nq],     &ah[4 * mf], &bh4[0]);
                    MMA_BF16(c[mf][2 * nq + 1], &ah[4 * mf], &bh4[2]);
                    MMA_BF16(c[mf][2 * nq],     &ah[4 * mf], &bl4[0]);
                    MMA_BF16(c[mf][2 * nq + 1], &ah[4 * mf], &bl4[2]);
                    MMA_BF16(c[mf][2 * nq],     &al[4 * mf], &bh4[0]);
                    MMA_BF16(c[mf][2 * nq + 1], &al[4 * mf], &bh4[2]);
                }
            }
        }
    }

    const int rb0 = m0 + wm * 32 + (lane >> 2);
    const int cb  = 2 * (lane & 3);

    if (mode == 0) {
        const int sel = n0 >> 10;
        const int nl  = (n0 & 1023) + wn * 64;
        const int h   = nl >> 6;
        __nv_bfloat16* dsth = (sel == 0) ? g_qhi : (sel == 1) ? g_khi : g_vhi;
        __nv_bfloat16* dstl = (sel == 0) ? g_qlo : (sel == 1) ? g_klo : g_vlo;
        const float* bias = ((sel == 0) ? bias0 : (sel == 1) ? bias1 : bias2)
                          + h * DH;
        const int b  = rb0 >> 11;
        const int s0 = rb0 & (SS - 1);
        size_t base = ((size_t)(b * NH + h) * SS) * DH;
#pragma unroll
        for (int mf = 0; mf < 2; mf++) {
#pragma unroll
            for (int nf = 0; nf < 8; nf++) {
                int d = nf * 8 + cb;
                float bx = bias[d], by = bias[d + 1];
                uint32_t h0, l0, h1, l1;
                split2u(c[mf][nf][0] + bx, c[mf][nf][1] + by, h0, l0);
                split2u(c[mf][nf][2] + bx, c[mf][nf][3] + by, h1, l1);
                size_t i0 = base + (size_t)(s0 + mf * 16) * DH + d;
                size_t i1 = base + (size_t)(s0 + mf * 16 + 8) * DH + d;
                *(uint32_t*)(dsth + i0) = h0;
                *(uint32_t*)(dstl + i0) = l0;
                *(uint32_t*)(dsth + i1) = h1;
                *(uint32_t*)(dstl + i1) = l1;
            }
        }
    } else {
        const int nb = n0 + wn * 64;
        const float* bias = bias0 + nb;
        float* op = outp + (size_t)rb0 * DM + nb;
#pragma unroll
        for (int mf = 0; mf < 2; mf++) {
#pragma unroll
            for (int nf = 0; nf < 8; nf++) {
                int d = nf * 8 + cb;
                float bx = bias[d], by = bias[d + 1];
                float2 v0 = make_float2(c[mf][nf][0] + bx, c[mf][nf][1] + by);
                float2 v1 = make_float2(c[mf][nf][2] + bx, c[mf][nf][3] + by);
                *(float2*)(op + (size_t)(mf * 16) * DM + d)     = v0;
                *(float2*)(op + (size_t)(mf * 16 + 8) * DM + d) = v1;
            }
        }
    }
}

// ---------------------------------------------------------------------------
// Causal flash attention (mma.sync bf16, 3-term split) — measured-best:
// 2-stage cp.async, single sync/tile, launch_bounds(256,1).
// ---------------------------------------------------------------------------
#define ADHP 72
#define AROWB (ADHP*2)
#define ATILE (64*AROWB)
#define AOFF_KHI 0
#define AOFF_KLO (ATILE)
#define AOFF_VHI (2*ATILE)
#define AOFF_VLO (3*ATILE)
#define ASTAGE (4*ATILE)               // 36864
#define ASMEM (2*ASTAGE)               // 73728

__device__ __forceinline__ void attn_load(uint32_t sbase,
    const __nv_bfloat16* Kh, const __nv_bfloat16* Kl,
    const __nv_bfloat16* Vh, const __nv_bfloat16* Vl,
    int j0, int tid)
{
#pragma unroll
    for (int i = 0; i < 2; i++) {
        int c   = tid + i * 256;
        int row = c >> 3;
        int co  = (c & 7) * 8;
        uint32_t soff = (uint32_t)(row * AROWB + co * 2);
        size_t goff = (size_t)(j0 + row) * DH + co;
        CP_ASYNC16(sbase + AOFF_KHI + soff, Kh + goff);
        CP_ASYNC16(sbase + AOFF_KLO + soff, Kl + goff);
        CP_ASYNC16(sbase + AOFF_VHI + soff, Vh + goff);
        CP_ASYNC16(sbase + AOFF_VLO + soff, Vl + goff);
    }
}

__global__ void __launch_bounds__(256, 1) attn_mma_kernel()
{
    extern __shared__ char smem[];
    const uint32_t sb0 = smem_to_u32(smem);

    const int tid  = threadIdx.x;
    const int lane = tid & 31;
    const int wq   = tid >> 5;
    const int bh   = blockIdx.y;
    const int qb   = (int)gridDim.x - 1 - (int)blockIdx.x;
    const int q0   = qb * 128;
    const int wr0  = q0 + wq * 16;

    const size_t hb = (size_t)bh * SS * DH;
    const __nv_bfloat16* Kh = g_khi + hb;
    const __nv_bfloat16* Kl = g_klo + hb;
    const __nv_bfloat16* Vh = g_vhi + hb;
    const __nv_bfloat16* Vl = g_vlo + hb;

    const int r0g = wr0 + (lane >> 2);
    const int r1g = r0g + 8;
    uint32_t qh[16], ql[16];
    {
        const __nv_bfloat16* Qh = g_qhi + hb;
        const __nv_bfloat16* Ql = g_qlo + hb;
        const int kb = 2 * (lane & 3);
#pragma unroll
        for (int t = 0; t < 4; t++) {
            int k0 = 16 * t + kb;
            qh[4*t+0] = *(const uint32_t*)(Qh + (size_t)r0g * DH + k0);
            qh[4*t+1] = *(const uint32_t*)(Qh + (size_t)r1g * DH + k0);
            qh[4*t+2] = *(const uint32_t*)(Qh + (size_t)r0g * DH + k0 + 8);
            qh[4*t+3] = *(const uint32_t*)(Qh + (size_t)r1g * DH + k0 + 8);
            ql[4*t+0] = *(const uint32_t*)(Ql + (size_t)r0g * DH + k0);
            ql[4*t+1] = *(const uint32_t*)(Ql + (size_t)r1g * DH + k0);
            ql[4*t+2] = *(const uint32_t*)(Ql + (size_t)r0g * DH + k0 + 8);
            ql[4*t+3] = *(const uint32_t*)(Ql + (size_t)r1g * DH + k0 + 8);
        }
    }

    float o[8][4];
#pragma unroll
    for (int i = 0; i < 8; i++)
#pragma unroll
        for (int j = 0; j < 4; j++) o[i][j] = 0.f;
    float m0 = -1e30f, m1 = -1e30f, l0 = 0.f, l1 = 0.f;

    const int kgrp = lane >> 3, kln = lane & 7;
    const uint32_t krow = (uint32_t)((kgrp >> 1) * 8 + kln);
    const uint32_t kcol = (uint32_t)((kgrp & 1) * 8);
    const uint32_t vrow = (uint32_t)((kgrp & 1) * 8 + kln);
    const uint32_t vcol = (uint32_t)((kgrp >> 1) * 8);

    const int ntk = 2 * qb + 2;
    attn_load(sb0, Kh, Kl, Vh, Vl, 0, tid);
    CP_COMMIT();

#pragma unroll 1
    for (int t = 0; t < ntk; t++) {
        CP_WAIT(0);
        __syncthreads();
        if (t + 1 < ntk) {
            attn_load(sb0 + ((t + 1) & 1) * ASTAGE, Kh, Kl, Vh, Vl,
                      (t + 1) * 64, tid);
            CP_COMMIT();
        }

        const int kv0 = t * 64;
        if (kv0 <= wr0 + 15) {
            const uint32_t st = sb0 + (t & 1) * ASTAGE;

            float s[8][4];
#pragma unroll
            for (int i = 0; i < 8; i++)
#pragma unroll
                for (int j = 0; j < 4; j++) s[i][j] = 0.f;

#pragma unroll
            for (int dk = 0; dk < 4; dk++) {
#pragma unroll
                for (int ng = 0; ng < 4; ng++) {
                    uint32_t kh4[4], kl4[4];
                    uint32_t ka = st + AOFF_KHI
                                + (uint32_t)(ng * 16 + krow) * AROWB
                                + (uint32_t)(dk * 16 + kcol) * 2;
                    LDSM_X4(kh4, ka);
                    LDSM_X4(kl4, ka + (AOFF_KLO - AOFF_KHI));
                    MMA_BF16(s[2*ng],   &qh[4*dk], &kh4[0]);
                    MMA_BF16(s[2*ng],   &ql[4*dk], &kh4[0]);
                    MMA_BF16(s[2*ng],   &qh[4*dk], &kl4[0]);
                    MMA_BF16(s[2*ng+1], &qh[4*dk], &kh4[2]);
                    MMA_BF16(s[2*ng+1], &ql[4*dk], &kh4[2]);
                    MMA_BF16(s[2*ng+1], &qh[4*dk], &kl4[2]);
                }
            }

            const bool needmask = (kv0 + 63 > wr0);
            const int colb = kv0 + 2 * (lane & 3);
#pragma unroll
            for (int nt = 0; nt < 8; nt++) {
                int c0 = colb + 8 * nt;
#pragma unroll
                for (int e = 0; e < 4; e++) {
                    float v = s[nt][e] * 0.125f;
                    if (needmask) {
                        int col = c0 + (e & 1);
                        int row = (e < 2) ? r0g : r1g;
                        if (col > row) v = -1e30f;
                    }
                    s[nt][e] = v;
                }
            }

            float t0 = -1e30f, t1 = -1e30f;
#pragma unroll
            for (int nt = 0; nt < 8; nt++) {
                t0 = fmaxf(t0, fmaxf(s[nt][0], s[nt][1]));
                t1 = fmaxf(t1, fmaxf(s[nt][2], s[nt][3]));
            }
            t0 = fmaxf(t0, __shfl_xor_sync(0xffffffff, t0, 1));
            t0 = fmaxf(t0, __shfl_xor_sync(0xffffffff, t0, 2));
            t1 = fmaxf(t1, __shfl_xor_sync(0xffffffff, t1, 1));
            t1 = fmaxf(t1, __shfl_xor_sync(0xffffffff, t1, 2));

            float mn0 = fmaxf(m0, t0), mn1 = fmaxf(m1, t1);
            float cr0 = __expf(m0 - mn0), cr1 = __expf(m1 - mn1);
            m0 = mn0; m1 = mn1;

            float ts0 = 0.f, ts1 = 0.f;
#pragma unroll
            for (int nt = 0; nt < 8; nt++) {
                s[nt][0] = __expf(s[nt][0] - m0);
                s[nt][1] = __expf(s[nt][1] - m0);
                s[nt][2] = __expf(s[nt][2] - m1);
                s[nt][3] = __expf(s[nt][3] - m1);
                ts0 += s[nt][0] + s[nt][1];
                ts1 += s[nt][2] + s[nt][3];
            }
            ts0 += __shfl_xor_sync(0xffffffff, ts0, 1);
            ts0 += __shfl_xor_sync(0xffffffff, ts0, 2);
            ts1 += __shfl_xor_sync(0xffffffff, ts1, 1);
            ts1 += __shfl_xor_sync(0xffffffff, ts1, 2);
            l0 = l0 * cr0 + ts0;
            l1 = l1 * cr1 + ts1;

#pragma unroll
            for (int nt = 0; nt < 8; nt++) {
                o[nt][0] *= cr0; o[nt][1] *= cr0;
                o[nt][2] *= cr1; o[nt][3] *= cr1;
            }

#pragma unroll
            for (int tp = 0; tp < 4; tp++) {
                uint32_t ph[4], pl[4];
                split2u(s[2*tp][0],   s[2*tp][1],   ph[0], pl[0]);
                split2u(s[2*tp][2],   s[2*tp][3],   ph[1], pl[1]);
                split2u(s[2*tp+1][0], s[2*tp+1][1], ph[2], pl[2]);
                split2u(s[2*tp+1][2], s[2*tp+1][3], ph[3], pl[3]);
#pragma unroll
                for (int dn2 = 0; dn2 < 4; dn2++) {
                    uint32_t vh4[4], vl4[4];
                    uint32_t va = st + AOFF_VHI
                                + (uint32_t)(tp * 16 + vrow) * AROWB
                                + (uint32_t)(dn2 * 16 + vcol) * 2;
                    LDSM_X4_T(vh4, va);
                    LDSM_X4_T(vl4, va + (AOFF_VLO - AOFF_VHI));
                    MMA_BF16(o[2*dn2],   ph, &vh4[0]);
                    MMA_BF16(o[2*dn2],   pl, &vh4[0]);
                    MMA_BF16(o[2*dn2],   ph, &vl4[0]);
                    MMA_BF16(o[2*dn2+1], ph, &vh4[2]);
                    MMA_BF16(o[2*dn2+1], pl, &vh4[2]);
                    MMA_BF16(o[2*dn2+1], ph, &vl4[2]);
                }
            }
        }
    }

    const float i0 = 1.f / l0, i1 = 1.f / l1;
    const int b = bh >> 4, h = bh & 15;
    const int cb = 2 * (lane & 3);
#pragma unroll
    for (int nt = 0; nt < 8; nt++) {
        int d = 8 * nt + cb;
        size_t z0 = ((size_t)(b * SS + r0g) * NH + h) * DH + d;
        size_t z1 = ((size_t)(b * SS + r1g) * NH + h) * DH + d;
        uint32_t h32, l32;
        split2u(o[nt][0] * i0, o[nt][1] * i0, h32, l32);
        *(uint32_t*)(g_zhi + z0) = h32;
        *(uint32_t*)(g_zlo + z0) = l32;
        split2u(o[nt][2] * i1, o[nt][3] * i1, h32, l32);
        *(uint32_t*)(g_zhi + z1) = h32;
        *(uint32_t*)(g_zlo + z1) = l32;
    }
}

// ---------------------------------------------------------------------------
// Launch sequence
// ---------------------------------------------------------------------------
extern "C" void kernel_launch(void* const* d_in, const int* in_sizes, int n_in,
                              void* d_out, int out_size)
{
    (void)in_sizes; (void)n_in; (void)out_size;
    const float* resid = (const float*)d_in[0];
    const float* Wq    = (const float*)d_in[1];
    const float* Wk    = (const float*)d_in[2];
    const float* Wv    = (const float*)d_in[3];
    const float* Wo    = (const float*)d_in[4];
    const float* bq    = (const float*)d_in[5];
    const float* bk    = (const float*)d_in[6];
    const float* bv    = (const float*)d_in[7];
    const float* bo    = (const float*)d_in[8];
    float* out = (float*)d_out;

    cudaFuncSetAttribute(mma_gemm_kernel,
                         cudaFuncAttributeMaxDynamicSharedMemorySize, SMEM_DYN);
    cudaFuncSetAttribute(attn_mma_kernel,
                         cudaFuncAttributeMaxDynamicSharedMemorySize, ASMEM);

    prep_kernel<<<6144, 256>>>(resid, Wq, Wk, Wv, Wo);

    mma_gemm_kernel<<<dim3(24, 64), 256, SMEM_DYN>>>(bq, bk, bv, nullptr, 0);
    attn_mma_kernel<<<dim3(16, 64), 256, ASMEM>>>();
    mma_gemm_kernel<<<dim3(8, 64), 256, SMEM_DYN>>>(bo, bo, bo, out, 1);
}

// round 17
// speedup vs baseline: 1.1593x; 1.0018x over previous
#include <cuda_runtime.h>
#include <cuda_bf16.h>
#include <cstdint>

// Problem constants
#define DM 1024      // d_model
#define NH 16        // n_heads
#define DH 64        // d_head
#define BB 4         // batch
#define SS 2048      // seq len
#define MR (BB*SS)   // 8192 rows

// ---------------------------------------------------------------------------
// Scratch (static device globals) — bf16 hi/lo everywhere, 16B-aligned
// ---------------------------------------------------------------------------
static __device__ __align__(16) __nv_bfloat16 g_qhi[(size_t)BB * NH * SS * DH];
static __device__ __align__(16) __nv_bfloat16 g_qlo[(size_t)BB * NH * SS * DH];
static __device__ __align__(16) __nv_bfloat16 g_khi[(size_t)BB * NH * SS * DH];
static __device__ __align__(16) __nv_bfloat16 g_klo[(size_t)BB * NH * SS * DH];
static __device__ __align__(16) __nv_bfloat16 g_vhi[(size_t)BB * NH * SS * DH];
static __device__ __align__(16) __nv_bfloat16 g_vlo[(size_t)BB * NH * SS * DH];
static __device__ __align__(16) __nv_bfloat16 g_zhi[(size_t)MR * DM];
static __device__ __align__(16) __nv_bfloat16 g_zlo[(size_t)MR * DM];

static __device__ __align__(16) __nv_bfloat16 g_xhi[(size_t)MR * DM];
static __device__ __align__(16) __nv_bfloat16 g_xlo[(size_t)MR * DM];
static __device__ __align__(16) __nv_bfloat16 g_wthi[(size_t)3 * DM * DM]; // [3072][1024]
static __device__ __align__(16) __nv_bfloat16 g_wtlo[(size_t)3 * DM * DM];
static __device__ __align__(16) __nv_bfloat16 g_wohi[(size_t)DM * DM];     // [1024][1024]
static __device__ __align__(16) __nv_bfloat16 g_wolo[(size_t)DM * DM];

// ---------------------------------------------------------------------------
// Base-arch PTX helpers
// ---------------------------------------------------------------------------
__device__ __forceinline__ uint32_t smem_to_u32(const void* p) {
    uint32_t a;
    asm("{ .reg .u64 t; cvta.to.shared.u64 t, %1; cvt.u32.u64 %0, t; }"
        : "=r"(a) : "l"(p));
    return a;
}

#define CP_ASYNC16(saddr, gptr) \
    asm volatile("cp.async.cg.shared.global [%0], [%1], 16;" \
        :: "r"(saddr), "l"(gptr))
#define CP_COMMIT() asm volatile("cp.async.commit_group;" ::: "memory")
#define CP_WAIT(n)  asm volatile("cp.async.wait_group %0;" :: "n"(n) : "memory")

#define LDSM_X4(r, addr) \
    asm volatile("ldmatrix.sync.aligned.m8n8.x4.shared.b16 {%0,%1,%2,%3}, [%4];" \
        : "=r"((r)[0]), "=r"((r)[1]), "=r"((r)[2]), "=r"((r)[3]) : "r"(addr))

#define LDSM_X4_T(r, addr) \
    asm volatile("ldmatrix.sync.aligned.m8n8.x4.trans.shared.b16 {%0,%1,%2,%3}, [%4];" \
        : "=r"((r)[0]), "=r"((r)[1]), "=r"((r)[2]), "=r"((r)[3]) : "r"(addr))

#define MMA_BF16(c, a, b) \
    asm volatile("mma.sync.aligned.m16n8k16.row.col.f32.bf16.bf16.f32 " \
        "{%0,%1,%2,%3}, {%4,%5,%6,%7}, {%8,%9}, {%0,%1,%2,%3};" \
        : "+f"((c)[0]), "+f"((c)[1]), "+f"((c)[2]), "+f"((c)[3]) \
        : "r"((a)[0]), "r"((a)[1]), "r"((a)[2]), "r"((a)[3]), \
          "r"((b)[0]), "r"((b)[1]))

// ---------------------------------------------------------------------------
// fp32 -> bf16 hi/lo split helpers
// ---------------------------------------------------------------------------
__device__ __forceinline__ void splitbf(float x, __nv_bfloat16 &h, __nv_bfloat16 &l) {
    h = __float2bfloat16(x);
    l = __float2bfloat16(x - __bfloat162float(h));
}

__device__ __forceinline__ void split2u(float x, float y, uint32_t &h32, uint32_t &l32) {
    __nv_bfloat16 hx, hy, lx, ly;
    splitbf(x, hx, lx);
    splitbf(y, hy, ly);
    __nv_bfloat162 th, tl;
    th.x = hx; th.y = hy;
    tl.x = lx; tl.y = ly;
    h32 = *(uint32_t*)&th;
    l32 = *(uint32_t*)&tl;
}

// ---------------------------------------------------------------------------
// Fused prep (vectorized): split X, convert Wqkv, convert Wo.
// blocks [0,4096): split_x ; [4096,5632): conv_wqkv ; [5632,6144): conv_wo
// ---------------------------------------------------------------------------
__global__ void __launch_bounds__(256) prep_kernel(
    const float* __restrict__ src,
    const float* __restrict__ Wq, const float* __restrict__ Wk,
    const float* __restrict__ Wv, const float* __restrict__ Wo)
{
    const int bid = blockIdx.x;
    const int tid = threadIdx.x;
    if (bid < 4096) {
        size_t i = (size_t)bid * 256 + tid;
        const float4* S = (const float4*)src;
        float4 v0 = S[2 * i], v1 = S[2 * i + 1];
        uint32_t h0, l0, h1, l1, h2, l2, h3, l3;
        split2u(v0.x, v0.y, h0, l0);
        split2u(v0.z, v0.w, h1, l1);
        split2u(v1.x, v1.y, h2, l2);
        split2u(v1.z, v1.w, h3, l3);
        ((uint4*)g_xhi)[i] = make_uint4(h0, h1, h2, h3);
        ((uint4*)g_xlo)[i] = make_uint4(l0, l1, l2, l3);
    } else if (bid < 4096 + 1536) {
        int idx = (bid - 4096) * 256 + tid;
        int n  = idx % 3072;
        int kb = idx / 3072;
        int sel = n >> 10, nl = n & 1023, h = nl >> 6, d = nl & 63;
        const float* W = (sel == 0) ? Wq : (sel == 1) ? Wk : Wv;
        const float* s = W + ((size_t)h << 16) + (size_t)(kb * 8) * DH + d;
        uint32_t hh[4], ll[4];
#pragma unroll
        for (int j = 0; j < 4; j++) {
            float x0 = s[(2 * j) * DH], x1 = s[(2 * j + 1) * DH];
            split2u(x0, x1, hh[j], ll[j]);
        }
        size_t o = ((size_t)n * DM + (size_t)kb * 8) >> 3;
        ((uint4*)g_wthi)[o] = make_uint4(hh[0], hh[1], hh[2], hh[3]);
        ((uint4*)g_wtlo)[o] = make_uint4(ll[0], ll[1], ll[2], ll[3]);
    } else {
        int idx = (bid - 5632) * 256 + tid;
        int n  = idx & 1023;
        int kb = idx >> 10;
        const float* s = Wo + (size_t)(kb * 8) * DM + n;
        uint32_t hh[4], ll[4];
#pragma unroll
        for (int j = 0; j < 4; j++) {
            float x0 = s[(2 * j) * DM], x1 = s[(2 * j + 1) * DM];
            split2u(x0, x1, hh[j], ll[j]);
        }
        size_t o = ((size_t)n * DM + (size_t)kb * 8) >> 3;
        ((uint4*)g_wohi)[o] = make_uint4(hh[0], hh[1], hh[2], hh[3]);
        ((uint4*)g_wolo)[o] = make_uint4(ll[0], ll[1], ll[2], ll[3]);
    }
}

// ---------------------------------------------------------------------------
// mma.sync bf16 GEMM (3-term split). CTA 128x128, 8 warps, K-chunk 32,
// 2-stage cp.async, single __syncthreads per k-tile.  (Measured best.)
// mode 0: A=X, B=Wqkv^T -> g_{q,k,v}{hi,lo} + bias
// mode 1: A=Z, B=Wo^T   -> fp32 out + bO (bias0)
// ---------------------------------------------------------------------------
#define KC 32
#define PADE 40
#define ROWB (PADE*2)
#define TILE_B (128*ROWB)
#define STAGE_B (4*TILE_B)
#define SMEM_DYN (2*STAGE_B)

__device__ __forceinline__ void load_stage(uint32_t sb,
    const __nv_bfloat16* Ah, const __nv_bfloat16* Al,
    const __nv_bfloat16* Bh, const __nv_bfloat16* Bl,
    int m0, int n0, int k0, int tid)
{
#pragma unroll
    for (int i = 0; i < 2; i++) {
        int c   = tid + i * 256;
        int row = c >> 2;
        int ko  = (c & 3) * 8;
        uint32_t soff = (uint32_t)(row * ROWB + (c & 3) * 16);
        CP_ASYNC16(sb + 0 * TILE_B + soff, Ah + (size_t)(m0 + row) * DM + k0 + ko);
        CP_ASYNC16(sb + 1 * TILE_B + soff, Al + (size_t)(m0 + row) * DM + k0 + ko);
        CP_ASYNC16(sb + 2 * TILE_B + soff, Bh + (size_t)(n0 + row) * DM + k0 + ko);
        CP_ASYNC16(sb + 3 * TILE_B + soff, Bl + (size_t)(n0 + row) * DM + k0 + ko);
    }
}

__global__ void __launch_bounds__(256, 2) mma_gemm_kernel(
    const float* __restrict__ bias0, const float* __restrict__ bias1,
    const float* __restrict__ bias2, float* __restrict__ outp, int mode)
{
    extern __shared__ char smem[];
    const uint32_t sb0 = smem_to_u32(smem);

    const int tid  = threadIdx.x;
    const int lane = tid & 31;
    const int wid  = tid >> 5;
    const int wm   = wid & 3;
    const int wn   = wid >> 2;
    const int m0   = blockIdx.y * 128;
    const int n0   = blockIdx.x * 128;

    const __nv_bfloat16* Ahi = (mode == 0) ? g_xhi  : g_zhi;
    const __nv_bfloat16* Alo = (mode == 0) ? g_xlo  : g_zlo;
    const __nv_bfloat16* Bhi = (mode == 0) ? g_wthi : g_wohi;
    const __nv_bfloat16* Blo = (mode == 0) ? g_wtlo : g_wolo;

    float c[2][8][4];
#pragma unroll
    for (int i = 0; i < 2; i++)
#pragma unroll
        for (int j = 0; j < 8; j++)
#pragma unroll
            for (int q = 0; q < 4; q++) c[i][j][q] = 0.f;

    const uint32_t a_row = (uint32_t)(wm * 32 + ((lane >> 3) & 1) * 8 + (lane & 7));
    const uint32_t a_kof = (uint32_t)((lane >> 4) * 8);
    const uint32_t b_row = (uint32_t)(wn * 64 + (lane >> 4) * 8 + (lane & 7));
    const uint32_t b_kof = (uint32_t)(((lane >> 3) & 1) * 8);

    load_stage(sb0, Ahi, Alo, Bhi, Blo, m0, n0, 0, tid);
    CP_COMMIT();

#pragma unroll 1
    for (int t = 0; t < DM / KC; t++) {
        CP_WAIT(0);
        __syncthreads();
        if (t + 1 < DM / KC) {
            load_stage(sb0 + ((t + 1) & 1) * STAGE_B, Ahi, Alo, Bhi, Blo,
                       m0, n0, (t + 1) * KC, tid);
            CP_COMMIT();
        }

        const uint32_t st = sb0 + (t & 1) * STAGE_B;
#pragma unroll
        for (int ks = 0; ks < 2; ks++) {
            const uint32_t k0 = (uint32_t)(ks * 16);
            uint32_t ah[8], al[8];
#pragma unroll
            for (int mf = 0; mf < 2; mf++) {
                uint32_t ad = st + (a_row + mf * 16) * ROWB + (k0 + a_kof) * 2;
                LDSM_X4(&ah[4 * mf], ad);
                LDSM_X4(&al[4 * mf], ad + TILE_B);
            }
#pragma unroll
            for (int nq = 0; nq < 4; nq++) {
                uint32_t bh4[4], bl4[4];
                uint32_t bd = st + 2 * TILE_B + (b_row + nq * 16) * ROWB
                            + (k0 + b_kof) * 2;
                LDSM_X4(bh4, bd);
                LDSM_X4(bl4, bd + TILE_B);
#pragma unroll
                for (int mf = 0; mf < 2; mf++) {
                    MMA_BF16(c[mf][2 * nq],     &ah[4 * mf], &bh4[0]);
                    MMA_BF16(c[mf][2 * nq + 1], &ah[4 * mf], &bh4[2]);
                    MMA_BF16(c[mf][2 * nq],     &ah[4 * mf], &bl4[0]);
                    MMA_BF16(c[mf][2 * nq + 1], &ah[4 * mf], &bl4[2]);
                    MMA_BF16(c[mf][2 * nq],     &al[4 * mf], &bh4[0]);
                    MMA_BF16(c[mf][2 * nq + 1], &al[4 * mf], &bh4[2]);
                }
            }
        }
    }

    const int rb0 = m0 + wm * 32 + (lane >> 2);
    const int cb  = 2 * (lane & 3);

    if (mode == 0) {
        const int sel = n0 >> 10;
        const int nl  = (n0 & 1023) + wn * 64;
        const int h   = nl >> 6;
        __nv_bfloat16* dsth = (sel == 0) ? g_qhi : (sel == 1) ? g_khi : g_vhi;
        __nv_bfloat16* dstl = (sel == 0) ? g_qlo : (sel == 1) ? g_klo : g_vlo;
        const float* bias = ((sel == 0) ? bias0 : (sel == 1) ? bias1 : bias2)
                          + h * DH;
        const int b  = rb0 >> 11;
        const int s0 = rb0 & (SS - 1);
        size_t base = ((size_t)(b * NH + h) * SS) * DH;
#pragma unroll
        for (int mf = 0; mf < 2; mf++) {
#pragma unroll
            for (int nf = 0; nf < 8; nf++) {
                int d = nf * 8 + cb;
                float bx = bias[d], by = bias[d + 1];
                uint32_t h0, l0, h1, l1;
                split2u(c[mf][nf][0] + bx, c[mf][nf][1] + by, h0, l0);
                split2u(c[mf][nf][2] + bx, c[mf][nf][3] + by, h1, l1);
                size_t i0 = base + (size_t)(s0 + mf * 16) * DH + d;
                size_t i1 = base + (size_t)(s0 + mf * 16 + 8) * DH + d;
                *(uint32_t*)(dsth + i0) = h0;
                *(uint32_t*)(dstl + i0) = l0;
                *(uint32_t*)(dsth + i1) = h1;
                *(uint32_t*)(dstl + i1) = l1;
            }
        }
    } else {
        const int nb = n0 + wn * 64;
        const float* bias = bias0 + nb;
        float* op = outp + (size_t)rb0 * DM + nb;
#pragma unroll
        for (int mf = 0; mf < 2; mf++) {
#pragma unroll
            for (int nf = 0; nf < 8; nf++) {
                int d = nf * 8 + cb;
                float bx = bias[d], by = bias[d + 1];
                float2 v0 = make_float2(c[mf][nf][0] + bx, c[mf][nf][1] + by);
                float2 v1 = make_float2(c[mf][nf][2] + bx, c[mf][nf][3] + by);
                *(float2*)(op + (size_t)(mf * 16) * DM + d)     = v0;
                *(float2*)(op + (size_t)(mf * 16 + 8) * DM + d) = v1;
            }
        }
    }
}

// ---------------------------------------------------------------------------
// Causal flash attention (mma.sync bf16, 3-term split) — measured-best:
// 2-stage cp.async, single sync/tile, launch_bounds(256,1).
// ---------------------------------------------------------------------------
#define ADHP 72
#define AROWB (ADHP*2)
#define ATILE (64*AROWB)
#define AOFF_KHI 0
#define AOFF_KLO (ATILE)
#define AOFF_VHI (2*ATILE)
#define AOFF_VLO (3*ATILE)
#define ASTAGE (4*ATILE)               // 36864
#define ASMEM (2*ASTAGE)               // 73728

__device__ __forceinline__ void attn_load(uint32_t sbase,
    const __nv_bfloat16* Kh, const __nv_bfloat16* Kl,
    const __nv_bfloat16* Vh, const __nv_bfloat16* Vl,
    int j0, int tid)
{
#pragma unroll
    for (int i = 0; i < 2; i++) {
        int c   = tid + i * 256;
        int row = c >> 3;
        int co  = (c & 7) * 8;
        uint32_t soff = (uint32_t)(row * AROWB + co * 2);
        size_t goff = (size_t)(j0 + row) * DH + co;
        CP_ASYNC16(sbase + AOFF_KHI + soff, Kh + goff);
        CP_ASYNC16(sbase + AOFF_KLO + soff, Kl + goff);
        CP_ASYNC16(sbase + AOFF_VHI + soff, Vh + goff);
        CP_ASYNC16(sbase + AOFF_VLO + soff, Vl + goff);
    }
}

__global__ void __launch_bounds__(256, 1) attn_mma_kernel()
{
    extern __shared__ char smem[];
    const uint32_t sb0 = smem_to_u32(smem);

    const int tid  = threadIdx.x;
    const int lane = tid & 31;
    const int wq   = tid >> 5;
    const int bh   = blockIdx.y;
    const int qb   = (int)gridDim.x - 1 - (int)blockIdx.x;
    const int q0   = qb * 128;
    const int wr0  = q0 + wq * 16;

    const size_t hb = (size_t)bh * SS * DH;
    const __nv_bfloat16* Kh = g_khi + hb;
    const __nv_bfloat16* Kl = g_klo + hb;
    const __nv_bfloat16* Vh = g_vhi + hb;
    const __nv_bfloat16* Vl = g_vlo + hb;

    const int r0g = wr0 + (lane >> 2);
    const int r1g = r0g + 8;
    uint32_t qh[16], ql[16];
    {
        const __nv_bfloat16* Qh = g_qhi + hb;
        const __nv_bfloat16* Ql = g_qlo + hb;
        const int kb = 2 * (lane & 3);
#pragma unroll
        for (int t = 0; t < 4; t++) {
            int k0 = 16 * t + kb;
            qh[4*t+0] = *(const uint32_t*)(Qh + (size_t)r0g * DH + k0);
            qh[4*t+1] = *(const uint32_t*)(Qh + (size_t)r1g * DH + k0);
            qh[4*t+2] = *(const uint32_t*)(Qh + (size_t)r0g * DH + k0 + 8);
            qh[4*t+3] = *(const uint32_t*)(Qh + (size_t)r1g * DH + k0 + 8);
            ql[4*t+0] = *(const uint32_t*)(Ql + (size_t)r0g * DH + k0);
            ql[4*t+1] = *(const uint32_t*)(Ql + (size_t)r1g * DH + k0);
            ql[4*t+2] = *(const uint32_t*)(Ql + (size_t)r0g * DH + k0 + 8);
            ql[4*t+3] = *(const uint32_t*)(Ql + (size_t)r1g * DH + k0 + 8);
        }
    }

    float o[8][4];
#pragma unroll
    for (int i = 0; i < 8; i++)
#pragma unroll
        for (int j = 0; j < 4; j++) o[i][j] = 0.f;
    float m0 = -1e30f, m1 = -1e30f, l0 = 0.f, l1 = 0.f;

    const int kgrp = lane >> 3, kln = lane & 7;
    const uint32_t krow = (uint32_t)((kgrp >> 1) * 8 + kln);
    const uint32_t kcol = (uint32_t)((kgrp & 1) * 8);
    const uint32_t vrow = (uint32_t)((kgrp & 1) * 8 + kln);
    const uint32_t vcol = (uint32_t)((kgrp >> 1) * 8);

    const int ntk = 2 * qb + 2;
    attn_load(sb0, Kh, Kl, Vh, Vl, 0, tid);
    CP_COMMIT();

#pragma unroll 1
    for (int t = 0; t < ntk; t++) {
        CP_WAIT(0);
        __syncthreads();
        if (t + 1 < ntk) {
            attn_load(sb0 + ((t + 1) & 1) * ASTAGE, Kh, Kl, Vh, Vl,
                      (t + 1) * 64, tid);
            CP_COMMIT();
        }

        const int kv0 = t * 64;
        if (kv0 <= wr0 + 15) {
            const uint32_t st = sb0 + (t & 1) * ASTAGE;

            float s[8][4];
#pragma unroll
            for (int i = 0; i < 8; i++)
#pragma unroll
                for (int j = 0; j < 4; j++) s[i][j] = 0.f;

#pragma unroll
            for (int dk = 0; dk < 4; dk++) {
#pragma unroll
                for (int ng = 0; ng < 4; ng++) {
                    uint32_t kh4[4], kl4[4];
                    uint32_t ka = st + AOFF_KHI
                                + (uint32_t)(ng * 16 + krow) * AROWB
                                + (uint32_t)(dk * 16 + kcol) * 2;
                    LDSM_X4(kh4, ka);
                    LDSM_X4(kl4, ka + (AOFF_KLO - AOFF_KHI));
                    MMA_BF16(s[2*ng],   &qh[4*dk], &kh4[0]);
                    MMA_BF16(s[2*ng],   &ql[4*dk], &kh4[0]);
                    MMA_BF16(s[2*ng],   &qh[4*dk], &kl4[0]);
                    MMA_BF16(s[2*ng+1], &qh[4*dk], &kh4[2]);
                    MMA_BF16(s[2*ng+1], &ql[4*dk], &kh4[2]);
                    MMA_BF16(s[2*ng+1], &qh[4*dk], &kl4[2]);
                }
            }

            const bool needmask = (kv0 + 63 > wr0);
            const int colb = kv0 + 2 * (lane & 3);
#pragma unroll
            for (int nt = 0; nt < 8; nt++) {
                int c0 = colb + 8 * nt;
#pragma unroll
                for (int e = 0; e < 4; e++) {
                    float v = s[nt][e] * 0.125f;
                    if (needmask) {
                        int col = c0 + (e & 1);
                        int row = (e < 2) ? r0g : r1g;
                        if (col > row) v = -1e30f;
                    }
                    s[nt][e] = v;
                }
            }

            float t0 = -1e30f, t1 = -1e30f;
#pragma unroll
            for (int nt = 0; nt < 8; nt++) {
                t0 = fmaxf(t0, fmaxf(s[nt][0], s[nt][1]));
                t1 = fmaxf(t1, fmaxf(s[nt][2], s[nt][3]));
            }
            t0 = fmaxf(t0, __shfl_xor_sync(0xffffffff, t0, 1));
            t0 = fmaxf(t0, __shfl_xor_sync(0xffffffff, t0, 2));
            t1 = fmaxf(t1, __shfl_xor_sync(0xffffffff, t1, 1));
            t1 = fmaxf(t1, __shfl_xor_sync(0xffffffff, t1, 2));

            float mn0 = fmaxf(m0, t0), mn1 = fmaxf(m1, t1);
            float cr0 = __expf(m0 - mn0), cr1 = __expf(m1 - mn1);
            m0 = mn0; m1 = mn1;

            float ts0 = 0.f, ts1 = 0.f;
#pragma unroll
            for (int nt = 0; nt < 8; nt++) {
                s[nt][0] = __expf(s[nt][0] - m0);
                s[nt][1] = __expf(s[nt][1] - m0);
                s[nt][2] = __expf(s[nt][2] - m1);
                s[nt][3] = __expf(s[nt][3] - m1);
                ts0 += s[nt][0] + s[nt][1];
                ts1 += s[nt][2] + s[nt][3];
            }
            ts0 += __shfl_xor_sync(0xffffffff, ts0, 1);
            ts0 += __shfl_xor_sync(0xffffffff, ts0, 2);
            ts1 += __shfl_xor_sync(0xffffffff, ts1, 1);
            ts1 += __shfl_xor_sync(0xffffffff, ts1, 2);
            l0 = l0 * cr0 + ts0;
            l1 = l1 * cr1 + ts1;

#pragma unroll
            for (int nt = 0; nt < 8; nt++) {
                o[nt][0] *= cr0; o[nt][1] *= cr0;
                o[nt][2] *= cr1; o[nt][3] *= cr1;
            }

#pragma unroll
            for (int tp = 0; tp < 4; tp++) {
                uint32_t ph[4], pl[4];
                split2u(s[2*tp][0],   s[2*tp][1],   ph[0], pl[0]);
                split2u(s[2*tp][2],   s[2*tp][3],   ph[1], pl[1]);
                split2u(s[2*tp+1][0], s[2*tp+1][1], ph[2], pl[2]);
                split2u(s[2*tp+1][2], s[2*tp+1][3], ph[3], pl[3]);
#pragma unroll
                for (int dn2 = 0; dn2 < 4; dn2++) {
                    uint32_t vh4[4], vl4[4];
                    uint32_t va = st + AOFF_VHI
                                + (uint32_t)(tp * 16 + vrow) * AROWB
                                + (uint32_t)(dn2 * 16 + vcol) * 2;
                    LDSM_X4_T(vh4, va);
                    LDSM_X4_T(vl4, va + (AOFF_VLO - AOFF_VHI));
                    MMA_BF16(o[2*dn2],   ph, &vh4[0]);
                    MMA_BF16(o[2*dn2],   pl, &vh4[0]);
                    MMA_BF16(o[2*dn2],   ph, &vl4[0]);
                    MMA_BF16(o[2*dn2+1], ph, &vh4[2]);
                    MMA_BF16(o[2*dn2+1], pl, &vh4[2]);
                    MMA_BF16(o[2*dn2+1], ph, &vl4[2]);
                }
            }
        }
    }

    const float i0 = 1.f / l0, i1 = 1.f / l1;
    const int b = bh >> 4, h = bh & 15;
    const int cb = 2 * (lane & 3);
#pragma unroll
    for (int nt = 0; nt < 8; nt++) {
        int d = 8 * nt + cb;
        size_t z0 = ((size_t)(b * SS + r0g) * NH + h) * DH + d;
        size_t z1 = ((size_t)(b * SS + r1g) * NH + h) * DH + d;
        uint32_t h32, l32;
        split2u(o[nt][0] * i0, o[nt][1] * i0, h32, l32);
        *(uint32_t*)(g_zhi + z0) = h32;
        *(uint32_t*)(g_zlo + z0) = l32;
        split2u(o[nt][2] * i1, o[nt][3] * i1, h32, l32);
        *(uint32_t*)(g_zhi + z1) = h32;
        *(uint32_t*)(g_zlo + z1) = l32;
    }
}

// ---------------------------------------------------------------------------
// Launch sequence
// ---------------------------------------------------------------------------
extern "C" void kernel_launch(void* const* d_in, const int* in_sizes, int n_in,
                              void* d_out, int out_size)
{
    (void)in_sizes; (void)n_in; (void)out_size;
    const float* resid = (const float*)d_in[0];
    const float* Wq    = (const float*)d_in[1];
    const float* Wk    = (const float*)d_in[2];
    const float* Wv    = (const float*)d_in[3];
    const float* Wo    = (const float*)d_in[4];
    const float* bq    = (const float*)d_in[5];
    const float* bk    = (const float*)d_in[6];
    const float* bv    = (const float*)d_in[7];
    const float* bo    = (const float*)d_in[8];
    float* out = (float*)d_out;

    cudaFuncSetAttribute(mma_gemm_kernel,
                         cudaFuncAttributeMaxDynamicSharedMemorySize, SMEM_DYN);
    cudaFuncSetAttribute(attn_mma_kernel,
                         cudaFuncAttributeMaxDynamicSharedMemorySize, ASMEM);

    prep_kernel<<<6144, 256>>>(resid, Wq, Wk, Wv, Wo);

    mma_gemm_kernel<<<dim3(24, 64), 256, SMEM_DYN>>>(bq, bk, bv, nullptr, 0);
    attn_mma_kernel<<<dim3(16, 64), 256, ASMEM>>>();
    mma_gemm_kernel<<<dim3(8, 64), 256, SMEM_DYN>>>(bo, bo, bo, out, 1);
}